// round 1
// baseline (speedup 1.0000x reference)
#include <cuda_runtime.h>
#include <cuda_bf16.h>
#include <math.h>

// Problem constants
#define Bb   64
#define NPG  400
#define Kk   250
#define Ff   64
#define LIN  16000
#define Hh   8000
#define Nn   (Bb*NPG)        // 25600
#define BN_EPS 1e-5f

// Scratch (device globals; no allocation allowed)
__device__ float           g_scores[Nn];
__device__ __nv_bfloat16   g_xn[Bb*LIN];
__device__ float           g_h[Bb*Hh];
__device__ float           g_logits[Bb];

// ---------------------------------------------------------------------------
// Kernel 1: per-node scores  score[n] = x[n,:] . w   (norm applied later)
// ---------------------------------------------------------------------------
__global__ void k_scores(const float* __restrict__ feat, const float* __restrict__ w) {
    int warp = threadIdx.x >> 5, lane = threadIdx.x & 31;
    int node = blockIdx.x * 8 + warp;
    const float* x = feat + (size_t)11 * Nn * Ff + (size_t)node * Ff;
    float v = x[lane] * w[lane] + x[lane + 32] * w[lane + 32];
    #pragma unroll
    for (int o = 16; o > 0; o >>= 1) v += __shfl_down_sync(0xffffffffu, v, o);
    if (lane == 0) g_scores[node] = v;
}

// ---------------------------------------------------------------------------
// Kernel 2: per-graph top-K (bitonic sort of 400 padded to 512, descending,
// ties -> lower index first), gather, tanh rescale, BatchNorm, write bf16 xn
// ---------------------------------------------------------------------------
__global__ void k_pool(const float* __restrict__ feat, const float* __restrict__ w,
                       const float* __restrict__ bn_mean, const float* __restrict__ bn_var,
                       const float* __restrict__ bn_gamma, const float* __restrict__ bn_beta) {
    __shared__ float sv[512];
    __shared__ int   si[512];
    __shared__ float s_inv;
    int tid = threadIdx.x, b = blockIdx.x;

    if (tid == 0) {
        float s = 0.f;
        #pragma unroll
        for (int i = 0; i < Ff; i++) s += w[i] * w[i];
        s_inv = rsqrtf(s);
    }
    sv[tid] = (tid < NPG) ? g_scores[b * NPG + tid] : __int_as_float(0xff800000); // -inf pad
    si[tid] = tid;
    __syncthreads();

    // Bitonic sort, final order: value descending, index ascending on ties
    for (int k = 2; k <= 512; k <<= 1) {
        for (int j = k >> 1; j > 0; j >>= 1) {
            int ixj = tid ^ j;
            if (ixj > tid) {
                float va = sv[tid], vb = sv[ixj];
                int   ia = si[tid], ib = si[ixj];
                bool aFirst = (va > vb) || (va == vb && ia < ib); // a should precede b (desc)
                bool bFirst = (vb > va) || (vb == va && ib < ia);
                bool desc = ((tid & k) == 0);
                bool sw = desc ? bFirst : aFirst;
                if (sw) { sv[tid] = vb; sv[ixj] = va; si[tid] = ib; si[ixj] = ia; }
            }
            __syncthreads();
        }
    }

    const float* x = feat + (size_t)11 * Nn * Ff + (size_t)b * NPG * Ff;
    float inv = s_inv;
    for (int i = tid; i < LIN; i += 512) {
        int r = i >> 6, f = i & 63;
        float sval = tanhf(sv[r] * inv);
        float xv = x[si[r] * Ff + f];
        float xn = (xv * sval - bn_mean[i]) * rsqrtf(bn_var[i] + BN_EPS) * bn_gamma[i] + bn_beta[i];
        g_xn[(size_t)b * LIN + i] = __float2bfloat16(xn);
    }
}

// ---------------------------------------------------------------------------
// Kernel 3: zero the split-K accumulator
// ---------------------------------------------------------------------------
__global__ void k_zero() {
    int i = blockIdx.x * blockDim.x + threadIdx.x;
    if (i < Bb * Hh) g_h[i] = 0.f;
}

// ---------------------------------------------------------------------------
// Kernel 4: GEMM1 (the big one)  h[m,j] += sum_k xn[m,k] * W1[j,k]
// W1 fp32 streamed from HBM, converted to bf16 in-register, MMA on tensor core.
// block: 256 threads (8 warps). BN=128 j-cols, all 64 m, BK=32, split-K=4.
// warp w owns j in [w*16, w*16+16): 2 n-tiles of 8; 4 m-tiles of 16.
// ---------------------------------------------------------------------------
#define BN1    128
#define BK1    32
#define KSPLIT 4
#define KCHUNK (LIN / KSPLIT)   // 4000
#define ITERS  (KCHUNK / BK1)   // 125
#define STW    (BK1 + 8)        // 40 halves -> 80B row stride (conflict-free frags)

__device__ __forceinline__ void mma16816(float* d,
                                         unsigned a0, unsigned a1, unsigned a2, unsigned a3,
                                         unsigned b0, unsigned b1) {
    asm volatile(
        "mma.sync.aligned.m16n8k16.row.col.f32.bf16.bf16.f32 "
        "{%0,%1,%2,%3}, {%4,%5,%6,%7}, {%8,%9}, {%0,%1,%2,%3};\n"
        : "+f"(d[0]), "+f"(d[1]), "+f"(d[2]), "+f"(d[3])
        : "r"(a0), "r"(a1), "r"(a2), "r"(a3), "r"(b0), "r"(b1));
}

__global__ __launch_bounds__(256, 2) void k_gemm1(const float* __restrict__ W1) {
    __shared__ __align__(16) __nv_bfloat16 smW[2][BN1][STW];
    __shared__ __align__(16) __nv_bfloat16 smX[2][64][STW];

    int tid  = threadIdx.x;
    int warp = tid >> 5, lane = tid & 31;
    int jbase = blockIdx.x * BN1;
    int kbase = blockIdx.y * KCHUNK;

    // W1 load mapping: c = float4 column (0..7), rgrp = row group (0..31), rows rgrp+u*32
    int c = tid & 7, rgrp = tid >> 3;
    // xn load mapping: xr = row 0..63, xs = 16B segment 0..3
    int xr = tid >> 2, xs = tid & 3;

    long rowAddr[4];
    #pragma unroll
    for (int u = 0; u < 4; u++) {
        int jr = jbase + rgrp + u * 32;
        if (jr > Hh - 1) jr = Hh - 1;           // clamp for partial last j-tile
        rowAddr[u] = (long)jr * LIN;
    }
    const __nv_bfloat16* xptr = g_xn + (size_t)xr * LIN;

    float4 rW[4];
    uint4  rX;
    float  acc[4][2][4];
    #pragma unroll
    for (int a = 0; a < 4; a++)
        #pragma unroll
        for (int b = 0; b < 2; b++)
            #pragma unroll
            for (int q = 0; q < 4; q++) acc[a][b][q] = 0.f;

    // prologue loads (stage 0)
    {
        int k0 = kbase;
        #pragma unroll
        for (int u = 0; u < 4; u++)
            rW[u] = *(const float4*)(W1 + rowAddr[u] + k0 + c * 4);
        rX = *(const uint4*)(xptr + k0 + xs * 8);
    }

    int gi = lane >> 2;   // group id (0..7)
    int qi = lane & 3;    // thread in group

    for (int it = 0; it < ITERS; it++) {
        int st = it & 1;

        // STS: convert W1 tile to bf16, copy xn tile
        #pragma unroll
        for (int u = 0; u < 4; u++) {
            __nv_bfloat16* d = &smW[st][rgrp + u * 32][c * 4];
            __nv_bfloat162 p0 = __floats2bfloat162_rn(rW[u].x, rW[u].y);
            __nv_bfloat162 p1 = __floats2bfloat162_rn(rW[u].z, rW[u].w);
            uint2 pk;
            pk.x = *(unsigned*)&p0;
            pk.y = *(unsigned*)&p1;
            *(uint2*)d = pk;
        }
        *(uint4*)(&smX[st][xr][xs * 8]) = rX;
        __syncthreads();

        // prefetch next chunk (overlaps with MMA below)
        if (it + 1 < ITERS) {
            int k0 = kbase + (it + 1) * BK1;
            #pragma unroll
            for (int u = 0; u < 4; u++)
                rW[u] = *(const float4*)(W1 + rowAddr[u] + k0 + c * 4);
            rX = *(const uint4*)(xptr + k0 + xs * 8);
        }

        // MMA over BK1 (two k16 chunks)
        #pragma unroll
        for (int kk = 0; kk < BK1; kk += 16) {
            unsigned a0[4], a1[4], a2[4], a3[4];
            #pragma unroll
            for (int mt = 0; mt < 4; mt++) {
                const __nv_bfloat16* ap = &smX[st][mt * 16 + gi][kk + qi * 2];
                a0[mt] = *(const unsigned*)(ap);
                a1[mt] = *(const unsigned*)(ap + 8 * STW);
                a2[mt] = *(const unsigned*)(ap + 8);
                a3[mt] = *(const unsigned*)(ap + 8 * STW + 8);
            }
            #pragma unroll
            for (int nt = 0; nt < 2; nt++) {
                const __nv_bfloat16* bp = &smW[st][warp * 16 + nt * 8 + gi][kk + qi * 2];
                unsigned b0 = *(const unsigned*)(bp);
                unsigned b1 = *(const unsigned*)(bp + 8);
                #pragma unroll
                for (int mt = 0; mt < 4; mt++)
                    mma16816(acc[mt][nt], a0[mt], a1[mt], a2[mt], a3[mt], b0, b1);
            }
        }
        __syncthreads();
    }

    // epilogue: split-K atomic accumulate into fp32 h[m][j]
    #pragma unroll
    for (int mt = 0; mt < 4; mt++) {
        #pragma unroll
        for (int nt = 0; nt < 2; nt++) {
            int m = mt * 16 + gi;
            int j = jbase + warp * 16 + nt * 8 + qi * 2;
            if (j < Hh) {
                atomicAdd(&g_h[m * Hh + j],           acc[mt][nt][0]);
                atomicAdd(&g_h[m * Hh + j + 1],       acc[mt][nt][1]);
                atomicAdd(&g_h[(m + 8) * Hh + j],     acc[mt][nt][2]);
                atomicAdd(&g_h[(m + 8) * Hh + j + 1], acc[mt][nt][3]);
            }
        }
    }
}

// ---------------------------------------------------------------------------
// Kernel 5: GEMM2 + bias + relu fused:  logits[m] = sum_j relu(h[m,j]+b1[j])*W2[j] + b2
// ---------------------------------------------------------------------------
__global__ void k_gemm2(const float* __restrict__ b1, const float* __restrict__ W2,
                        const float* __restrict__ b2) {
    int m = blockIdx.x, tid = threadIdx.x;
    const float* hp = g_h + (size_t)m * Hh;
    float s = 0.f;
    for (int j = tid; j < Hh; j += 256)
        s += fmaxf(hp[j] + b1[j], 0.f) * W2[j];
    #pragma unroll
    for (int o = 16; o > 0; o >>= 1) s += __shfl_down_sync(0xffffffffu, s, o);
    __shared__ float red[8];
    if ((tid & 31) == 0) red[tid >> 5] = s;
    __syncthreads();
    if (tid < 8) {
        s = red[tid];
        #pragma unroll
        for (int o = 4; o > 0; o >>= 1) s += __shfl_down_sync(0xffu, s, o);
        if (tid == 0) g_logits[m] = s + b2[0];
    }
}

// ---------------------------------------------------------------------------
// Kernel 6: BCE-with-logits loss vs target=1:  mean(softplus(l) - l)
// ---------------------------------------------------------------------------
__global__ void k_loss(float* __restrict__ out) {
    int tid = threadIdx.x;  // 64 threads
    float l = g_logits[tid];
    float per = (l > 0.f) ? log1pf(expf(-l)) : (log1pf(expf(l)) - l);
    #pragma unroll
    for (int o = 16; o > 0; o >>= 1) per += __shfl_down_sync(0xffffffffu, per, o);
    __shared__ float r2[2];
    if ((tid & 31) == 0) r2[tid >> 5] = per;
    __syncthreads();
    if (tid == 0) out[0] = (r2[0] + r2[1]) * (1.0f / Bb);
}

// ---------------------------------------------------------------------------
extern "C" void kernel_launch(void* const* d_in, const int* in_sizes, int n_in,
                              void* d_out, int out_size) {
    const float* feat     = (const float*)d_in[0];
    // d_in[1] edge_index, d_in[2] batch: unused (graphs contiguous, ref ignores edges)
    const float* w        = (const float*)d_in[3];
    const float* bn_gamma = (const float*)d_in[4];
    const float* bn_beta  = (const float*)d_in[5];
    const float* bn_mean  = (const float*)d_in[6];
    const float* bn_var   = (const float*)d_in[7];
    const float* W1       = (const float*)d_in[8];
    const float* b1       = (const float*)d_in[9];
    const float* W2       = (const float*)d_in[10];
    const float* b2       = (const float*)d_in[11];

    k_zero<<<(Bb * Hh + 255) / 256, 256>>>();
    k_scores<<<Nn / 8, 256>>>(feat, w);
    k_pool<<<Bb, 512>>>(feat, w, bn_mean, bn_var, bn_gamma, bn_beta);
    dim3 g1(63, KSPLIT);  // ceil(8000/128) x split-K
    k_gemm1<<<g1, 256>>>(W1);
    k_gemm2<<<Bb, 256>>>(b1, W2, b2);
    k_loss<<<1, 64>>>((float*)d_out);
}